// round 1
// baseline (speedup 1.0000x reference)
#include <cuda_runtime.h>
#include <cooperative_groups.h>
#include <cstdint>

namespace cg = cooperative_groups;

// Problem constants (fixed by the dataset)
constexpr int B = 32;
constexpr int N = 131072;
constexpr int K = 1024;

// Kernel config
constexpr int C  = 4;          // CTAs per batch (cluster size)
constexpr int T  = 1024;       // threads per CTA
constexpr int S  = N / C;      // 32768 points per CTA slice
constexpr int SP = 8192;       // points pinned in SMEM per CTA
constexpr int SJ = SP / T;     // 8  smem-point iters per thread
constexpr int GJ = (S - SP) / T; // 24 streamed-point iters per thread

// SoA scratch for coalesced loads (static device arrays: allocation-free)
__device__ float g_sx[B * N];
__device__ float g_sy[B * N];
__device__ float g_sz[B * N];

__global__ void transpose_kernel(const float* __restrict__ pts) {
    int i = blockIdx.x * blockDim.x + threadIdx.x;
    if (i < B * N) {
        g_sx[i] = pts[3 * i + 0];
        g_sy[i] = pts[3 * i + 1];
        g_sz[i] = pts[3 * i + 2];
    }
}

// Dynamic SMEM layout (bytes)
constexpr int SMEM_DIST = 0;                  // S floats   = 131072 B
constexpr int SMEM_PX   = SMEM_DIST + S * 4;  // SP floats  =  32768 B
constexpr int SMEM_PY   = SMEM_PX + SP * 4;
constexpr int SMEM_PZ   = SMEM_PY + SP * 4;
constexpr int SMEM_EX   = SMEM_PZ + SP * 4;   // 2 x u64 exchange slots (parity)
constexpr int SMEM_WB   = SMEM_EX + 16;       // 32 x u64 warp-reduce scratch
constexpr int SMEM_SB   = SMEM_WB + 256;      // broadcast last-point coords
constexpr int SMEM_TOTAL = SMEM_SB + 16;      // = 229,668 -> fits 227KB opt-in

__global__ void __cluster_dims__(C, 1, 1) __launch_bounds__(T, 1)
fps_kernel(const int* __restrict__ init_idx, float* __restrict__ out)
{
    extern __shared__ char smem[];
    float* sdist = (float*)(smem + SMEM_DIST);
    float* sx    = (float*)(smem + SMEM_PX);
    float* sy    = (float*)(smem + SMEM_PY);
    float* sz    = (float*)(smem + SMEM_PZ);
    unsigned long long* ex = (unsigned long long*)(smem + SMEM_EX);
    unsigned long long* wb = (unsigned long long*)(smem + SMEM_WB);
    float* sb    = (float*)(smem + SMEM_SB);

    cg::cluster_group cluster = cg::this_cluster();
    const int rank  = blockIdx.x;        // 0..C-1 within cluster
    const int b     = blockIdx.y;        // batch
    const int t     = threadIdx.x;
    const int lbase = rank * S;          // slice start (index within batch)
    const int gbase = b * N + lbase;     // slice start in SoA arrays
    const int warp  = t >> 5, lane = t & 31;

    // ---- one-time init: pin point subset + dist into SMEM ----
    #pragma unroll
    for (int j = 0; j < SJ; j++) {
        int i = t + j * T;
        sx[i] = g_sx[gbase + i];
        sy[i] = g_sy[gbase + i];
        sz[i] = g_sz[gbase + i];
    }
    #pragma unroll
    for (int j = 0; j < S / T; j++) sdist[t + j * T] = 1e10f;

    if (t == 0) {
        int idx0 = init_idx[b];
        float lx = g_sx[b * N + idx0];
        float ly = g_sy[b * N + idx0];
        float lz = g_sz[b * N + idx0];
        sb[0] = lx; sb[1] = ly; sb[2] = lz;
        if (rank == 0) {
            out[(b * K + 0) * 3 + 0] = lx;
            out[(b * K + 0) * 3 + 1] = ly;
            out[(b * K + 0) * 3 + 2] = lz;
        }
    }
    __syncthreads();

    // ---- K-1 sequential FPS iterations ----
    for (int k = 1; k < K; k++) {
        const float lx = sb[0], ly = sb[1], lz = sb[2];
        unsigned long long best = 0ULL;

        // SMEM-pinned points
        #pragma unroll
        for (int j = 0; j < SJ; j++) {
            int l = t + j * T;
            float dx = sx[l] - lx, dy = sy[l] - ly, dz = sz[l] - lz;
            float d2 = dx * dx + dy * dy + dz * dz;
            float dc = sdist[l];
            if (d2 < dc) { sdist[l] = d2; dc = d2; }
            unsigned long long cand =
                ((unsigned long long)__float_as_uint(dc) << 32) |
                (unsigned)(~(unsigned)(lbase + l));
            if (cand > best) best = cand;
        }
        // L2-streamed points
        #pragma unroll 4
        for (int j = 0; j < GJ; j++) {
            int l = SP + t + j * T;
            int g = gbase + l;
            float dx = g_sx[g] - lx, dy = g_sy[g] - ly, dz = g_sz[g] - lz;
            float d2 = dx * dx + dy * dy + dz * dz;
            float dc = sdist[l];
            if (d2 < dc) { sdist[l] = d2; dc = d2; }
            unsigned long long cand =
                ((unsigned long long)__float_as_uint(dc) << 32) |
                (unsigned)(~(unsigned)(lbase + l));
            if (cand > best) best = cand;
        }

        // warp-level max of packed (dist, ~idx)
        #pragma unroll
        for (int o = 16; o > 0; o >>= 1) {
            unsigned long long v = __shfl_down_sync(0xffffffffu, best, o);
            if (v > best) best = v;
        }
        if (lane == 0) wb[warp] = best;
        __syncthreads();
        if (warp == 0) {
            best = wb[lane];
            #pragma unroll
            for (int o = 16; o > 0; o >>= 1) {
                unsigned long long v = __shfl_down_sync(0xffffffffu, best, o);
                if (v > best) best = v;
            }
            if (lane == 0) ex[k & 1] = best;  // publish in own SMEM (parity slot)
        }

        cluster.sync();  // orders slot writes; peers then read via DSMEM

        if (t == 0) {
            unsigned long long gb = 0ULL;
            #pragma unroll
            for (int r = 0; r < C; r++) {
                unsigned long long* rp = cluster.map_shared_rank(&ex[k & 1], r);
                unsigned long long v = *rp;
                if (v > gb) gb = v;
            }
            unsigned idx = ~(unsigned)(gb & 0xffffffffull);
            float nlx = g_sx[b * N + idx];  // L2 hit
            float nly = g_sy[b * N + idx];
            float nlz = g_sz[b * N + idx];
            sb[0] = nlx; sb[1] = nly; sb[2] = nlz;
            if (rank == 0) {
                out[(b * K + k) * 3 + 0] = nlx;
                out[(b * K + k) * 3 + 1] = nly;
                out[(b * K + k) * 3 + 2] = nlz;
            }
        }
        __syncthreads();
    }

    // keep SMEM alive until all peers finished their last DSMEM reads
    cluster.sync();
}

extern "C" void kernel_launch(void* const* d_in, const int* in_sizes, int n_in,
                              void* d_out, int out_size) {
    const float* pts  = (const float*)d_in[0];
    const int*   init = (const int*)d_in[1];
    float*       out  = (float*)d_out;

    // idempotent, not a stream op: safe under graph capture
    cudaFuncSetAttribute(fps_kernel,
                         cudaFuncAttributeMaxDynamicSharedMemorySize, SMEM_TOTAL);

    int total = B * N;
    transpose_kernel<<<(total + 255) / 256, 256>>>(pts);

    dim3 grid(C, B, 1);
    fps_kernel<<<grid, T, SMEM_TOTAL>>>(init, out);
}